// round 12
// baseline (speedup 1.0000x reference)
#include <cuda_runtime.h>
#include <math.h>

#define BB 8
#define H 256
#define W 256
#define NPIX (H*W)
#define GRID 128
#define LUTN 1024

// Scratch (device globals — no allocation allowed)
__device__ float g_pd[GRID];
__device__ float g_d [GRID];
__device__ float g_mx[GRID];
__device__ unsigned int g_t = 0;

__device__ __forceinline__ float fast_sigmoid(float x) {
    float th;
    asm("tanh.approx.f32 %0, %1;" : "=f"(th) : "f"(x * 0.5f));
    return fmaf(0.5f, th, 0.5f);
}

// Block = (image b, 32-col group g, row half). Fully self-sufficient:
// loads target cols [colbase-32, colbase+64) x all 256 rows, builds boundary
// bits, exact vertical distances for its 128 rows x 96 cols, then exact
// min-plus (scan radius <= 31 cols; exact whenever the early exit fires,
// which holds for any m < 961) for its 32 center cols.
__global__ void __launch_bounds__(256)
k_fused(const float* __restrict__ logits, const int* __restrict__ target,
        float* __restrict__ out) {
    __shared__ unsigned int tb[H][3];          // packed bits, later boundary
    __shared__ unsigned int hm[H][3];          // horizontal 3-AND
    __shared__ unsigned int cmw[96][9];        // column masks (padded stride)
    __shared__ unsigned short f2s[128][96];    // vertical distance (not squared)
    __shared__ float s_lut[LUTN];
    __shared__ float rs[8], rp[8], rm[8];
    __shared__ double sper[BB];
    __shared__ bool amLast;

    int bid = blockIdx.x, tid = threadIdx.x;
    int w = tid >> 5, lane = tid & 31;
    int b = bid >> 4;                          // image
    int g = (bid >> 1) & 7;                    // 32-col group
    int half = bid & 1;                        // row half (128 rows)
    int colbase = g << 5;
    const int* t = target + b * NPIX;

    // sqrt LUT (exact sqrtf values for integer m)
    #pragma unroll
    for (int k = 0; k < 4; k++) {
        int idx = tid + k * 256;
        s_lut[idx] = sqrtf((float)idx);
    }

    // ---- pack 3 words/row + horizontal 3-AND (warp w: rows 32w..32w+31) ----
    {
        int r0 = w << 5;
        #pragma unroll 4
        for (int rr = 0; rr < 32; rr++) {
            int r = r0 + rr;
            int base = r * W + colbase - 32 + lane;
            int v0 = (g > 0) ? t[base] : 0;            // cols colbase-32..-1
            int v1 = t[base + 32];                     // center cols
            int v2 = (g < 7) ? t[base + 64] : 0;       // cols colbase+32..63
            unsigned int m0 = __ballot_sync(~0u, v0 != 0);
            unsigned int m1 = __ballot_sync(~0u, v1 != 0);
            unsigned int m2 = __ballot_sync(~0u, v2 != 0);
            // horizontal AND; out-of-window neighbors are 0 (matches zero pad)
            unsigned int h0 = m0 & (m0 << 1) & ((m0 >> 1) | (m1 << 31));
            unsigned int h1 = m1 & ((m1 << 1) | (m0 >> 31)) & ((m1 >> 1) | (m2 << 31));
            unsigned int h2 = m2 & ((m2 << 1) | (m1 >> 31)) & (m2 >> 1);
            if (lane == 0) {
                tb[r][0] = m0; tb[r][1] = m1; tb[r][2] = m2;
                hm[r][0] = h0; hm[r][1] = h1; hm[r][2] = h2;
            }
        }
    }
    __syncthreads();

    // ---- vertical 3-AND -> erosion; boundary = tb ^ er (in place) ----------
    #pragma unroll
    for (int k = 0; k < 3; k++) {
        int id = tid + k * 256;                 // 768 word-tasks
        int r = id / 3, G = id - r * 3;
        unsigned int er = (r > 0 && r < H - 1)
                        ? (hm[r-1][G] & hm[r][G] & hm[r+1][G]) : 0u;
        tb[r][G] ^= er;                         // reads own word only
    }
    __syncthreads();

    // ---- 32x32 bit transpose: warp w = slab w, 3 groups -> column masks ----
    {
        #pragma unroll
        for (int G = 0; G < 3; G++) {
            unsigned int word = tb[(w << 5) + lane][G];
            unsigned int v = 0u;
            #pragma unroll
            for (int jj = 0; jj < 32; jj++) {
                unsigned int bm = __ballot_sync(~0u, (word >> jj) & 1u);
                if (lane == jj) v = bm;
            }
            cmw[G * 32 + lane][w] = v;          // col G*32+lane, slab w
        }
    }
    __syncthreads();

    // ---- exact vertical distance for our half's 128 rows x 96 cols ---------
    #pragma unroll
    for (int k = 0; k < 2; k++) {
        int id = tid + k * 256;
        if (id < 384) {                         // 96 cols x 4 slabs
            int sl = id / 96;                   // slab within half (0..3)
            int c  = id - sl * 96;              // column (0..95)
            int s  = (half << 2) + sl;          // global slab
            unsigned int cmv[8];
            #pragma unroll
            for (int q = 0; q < 8; q++) cmv[q] = cmw[c][q];
            int P = -1000000, N = 1000000;
            #pragma unroll
            for (int q = 0; q < 8; q++) {
                if (q < s && cmv[q]) P = (q << 5) + 31 - __clz(cmv[q]);
                if (q > s && cmv[q] && N == 1000000) N = (q << 5) + __ffs(cmv[q]) - 1;
            }
            unsigned int vv = cmv[s];
            int rowg = s << 5;
            #pragma unroll
            for (int i = 0; i < 32; i++) {
                unsigned int below = vv & (0xFFFFFFFFu >> (31 - i));
                unsigned int above = vv & (0xFFFFFFFFu << i);
                int row = rowg + i;
                int last = below ? (rowg + 31 - __clz(below)) : P;
                int nxt  = above ? (rowg + __ffs(above) - 1) : N;
                int f = min(min(row - last, nxt - row), 10000);  // BIG clip
                f2s[(sl << 5) + i][c] = (unsigned short)f;
            }
        }
    }
    __syncthreads();

    // ---- min-plus (exact int arithmetic) + sigmoid + accumulate ------------
    // 16 rows per thread; candidate = f'^2 + o^2, all exact ints < 2^31,
    // identical values to the reference's fp32 path for every reachable case.
    float sd = 0.f, sp = 0.f, mxv = 0.f;
    int gbase = (b * H + (half << 7) + (w << 4)) * W + colbase + lane;
    #pragma unroll 4
    for (int k = 0; k < 16; k++) {
        const unsigned short* fr = f2s[(w << 4) + k];
        int f0 = fr[32 + lane];
        int m = f0 * f0;
        int o = 1;
        while (o * o < m && o < 32) {
            int c1 = fr[32 + lane - o];
            int c2 = fr[32 + lane + o];
            int oo = o * o;
            m = min(m, c1 * c1 + oo);
            m = min(m, c2 * c2 + oo);
            o++;
        }
        float d = (m < LUTN) ? s_lut[m] : sqrtf((float)m);
        float pred = fast_sigmoid(logits[gbase + k * W]);
        sd += d;
        sp += pred * d;
        mxv = fmaxf(mxv, d);
    }

    // ---- deterministic block reduction -> per-block partials ---------------
    #pragma unroll
    for (int o = 16; o; o >>= 1) {
        sd  += __shfl_down_sync(~0u, sd,  o);
        sp  += __shfl_down_sync(~0u, sp,  o);
        mxv  = fmaxf(mxv, __shfl_down_sync(~0u, mxv, o));
    }
    if (lane == 0) { rs[w] = sd; rp[w] = sp; rm[w] = mxv; }
    __syncthreads();
    if (tid == 0) {
        float S = 0.f, Pp = 0.f, M = 0.f;
        #pragma unroll
        for (int k = 0; k < 8; k++) { S += rs[k]; Pp += rp[k]; M = fmaxf(M, rm[k]); }
        g_d[bid] = S; g_pd[bid] = Pp; g_mx[bid] = M;
        __threadfence();
        amLast = (atomicAdd(&g_t, 1u) == GRID - 1);
    }
    __syncthreads();
    if (!amLast) return;

    // ---- final reduction (last block): warp w = image w, lanes 0..15 -------
    {
        double sdd = 0.0, spp = 0.0;
        float mxx = 0.f;
        if (lane < 16) {
            int idx = w * 16 + lane;            // 16 partials per image
            sdd = (double)g_d[idx];
            spp = (double)g_pd[idx];
            mxx = g_mx[idx];
        }
        #pragma unroll
        for (int o = 8; o; o >>= 1) {
            sdd += __shfl_down_sync(~0u, sdd, o);
            spp += __shfl_down_sync(~0u, spp, o);
            mxx  = fmaxf(mxx, __shfl_down_sync(~0u, mxx, o));
        }
        if (lane == 0)
            sper[w] = spp / (sdd + 1e-7 * ((double)mxx + 1e-7));
        __syncthreads();
        if (tid == 0) {
            double acc = 0.0;
            #pragma unroll
            for (int k = 0; k < BB; k++) acc += sper[k];
            out[0] = (float)(acc / BB);
            g_t = 0;                            // reset for next graph replay
        }
    }
}

extern "C" void kernel_launch(void* const* d_in, const int* in_sizes, int n_in,
                              void* d_out, int out_size) {
    const float* logits = (const float*)d_in[0];
    const int*   target = (const int*)d_in[1];
    float* out = (float*)d_out;

    k_fused<<<GRID, 256>>>(logits, target, out);
}

// round 13
// speedup vs baseline: 1.2936x; 1.2936x over previous
#include <cuda_runtime.h>
#include <math.h>

#define BB 8
#define H 256
#define W 256
#define NPIX (H*W)
#define GRID 128
#define NPREP 16
#define LUTN 1024

// Scratch (device globals — no allocation allowed)
__device__ unsigned int g_cm[BB*W*8];    // column seed masks: [(b*W+j)*8 + slab]
__device__ float g_pd[GRID], g_d[GRID], g_mx[GRID];
__device__ unsigned int g_barA = 0;      // phase-A arrival counter (blocks)
__device__ unsigned int g_t = 0;         // completion ticket

struct PhaseA {
    unsigned int tb[H];
    unsigned int hm[H];
    unsigned int Lm[8], Rm[8];
};

union SmemU {
    PhaseA a[4];                          // 4 units x 2112B = 8448B
    unsigned short f[4][4][3*W];          // [unit][row][padded col] = 24576B
};

__device__ __forceinline__ float fast_sigmoid(float x) {
    float th;
    asm("tanh.approx.f32 %0, %1;" : "=f"(th) : "f"(x * 0.5f));
    return fmaf(0.5f, th, 0.5f);
}

__global__ void __launch_bounds__(1024, 1)
k_fused(const float* __restrict__ logits, const int* __restrict__ target,
        float* __restrict__ out) {
    __shared__ SmemU u;
    __shared__ float s_lut[LUTN];
    __shared__ float rs[4][8], rp[4][8], rm[4][8];
    __shared__ float us[4], up[4], um[4];
    __shared__ double sper[BB];
    __shared__ bool amLast;

    int bid = blockIdx.x, tid = threadIdx.x;
    int u4 = tid >> 8, ut = tid & 255;    // virtual unit, tid within unit
    int w = ut >> 5, lane = tid & 31;     // warp within unit (warps don't straddle units)
    int vb = (bid << 2) | u4;             // virtual bid 0..511 (matches R10 layout)

    // ====== Phase A (blocks 0..15 => vb 0..63): (image, col-group) stripe ===
    if (bid < NPREP) {
        int b = vb >> 3, g = vb & 7;
        const int* t = target + b * NPIX;
        int colbase = g << 5;
        PhaseA& A = u.a[u4];

        // pack: warp w packs rows 32w..32w+31; batch 16 loads -> 16 ballots
        #pragma unroll
        for (int batch = 0; batch < 2; batch++) {
            int v[16];
            #pragma unroll
            for (int r = 0; r < 16; r++) {
                int i = (w << 5) + batch * 16 + r;
                v[r] = t[i * W + colbase + lane];
            }
            #pragma unroll
            for (int r = 0; r < 16; r++) {
                unsigned int m = __ballot_sync(0xffffffffu, v[r] != 0);
                if (lane == 0) A.tb[(w << 5) + batch * 16 + r] = m;
            }
        }
        // halo columns (lane = row within slab)
        {
            int i = (w << 5) + lane;
            int Lv = (g > 0) ? t[i * W + colbase - 1]  : 0;
            int Rv = (g < 7) ? t[i * W + colbase + 32] : 0;
            unsigned int lm  = __ballot_sync(0xffffffffu, Lv != 0);
            unsigned int rm2 = __ballot_sync(0xffffffffu, Rv != 0);
            if (lane == 0) { A.Lm[w] = lm; A.Rm[w] = rm2; }
        }
        __syncthreads();

        // horizontal 3-AND (thread = row within unit)
        {
            int i = ut;
            unsigned int c  = A.tb[i];
            unsigned int Lb = (A.Lm[i >> 5] >> (i & 31)) & 1u;
            unsigned int Rb = (A.Rm[i >> 5] >> (i & 31)) & 1u;
            unsigned int lf = (c << 1) | Lb;
            unsigned int rt = (c >> 1) | (Rb << 31);
            A.hm[i] = c & lf & rt;
        }
        __syncthreads();

        // vertical 3-AND -> erosion; boundary = tb ^ er (borders erode false)
        unsigned int bdw;
        {
            int i = ut;
            unsigned int er = (i > 0 && i < H - 1)
                            ? (A.hm[i - 1] & A.hm[i] & A.hm[i + 1]) : 0u;
            if (g == 0) er &= ~1u;
            if (g == 7) er &= ~(1u << 31);
            bdw = A.tb[i] ^ er;
        }
        __syncthreads();
        A.tb[ut] = bdw;
        __syncthreads();

        // 32x32 bit transpose per warp; lane j gets column j's slab bits
        unsigned int word = A.tb[(w << 5) + lane];
        unsigned int v = 0u;
        #pragma unroll
        for (int jj = 0; jj < 32; jj++) {
            unsigned int bm = __ballot_sync(0xffffffffu, (word >> jj) & 1u);
            if (lane == jj) v = bm;
        }
        g_cm[((b * W) + colbase + lane) * 8 + w] = v;

        __threadfence();
        __syncthreads();
        if (tid == 0) atomicAdd(&g_barA, 1u);
    }

    // ====== Pre-barrier work with no phase-A dependency =====================
    s_lut[tid] = sqrtf((float)tid);       // 1024 threads -> full LUT

    int pb = vb >> 6;                     // phase-B image
    int i0 = (vb & 63) * 4;               // phase-B first row (same 32-row slab)
    int j = ut;                           // phase-B column
    float xl[4];
    #pragma unroll
    for (int r = 0; r < 4; r++)
        xl[r] = logits[(pb * H + i0 + r) * W + j];

    #pragma unroll
    for (int r = 0; r < 4; r++) {         // pads: f=10000 -> candidate >= 1e8
        u.f[u4][r][j] = 10000;
        u.f[u4][r][2 * W + j] = 10000;
    }

    // ====== Grid barrier (prep blocks dispatched first) =====================
    if (tid == 0) {
        while (*(volatile unsigned int*)&g_barA < NPREP) __nanosleep(32);
    }
    __syncthreads();

    // ====== Phase B: vertical distance from bitmask + exact int min-plus ====
    const uint4* cmp = (const uint4*)&g_cm[((pb * W) + j) * 8];
    uint4 lov = cmp[0], hiv = cmp[1];
    unsigned int cm[8] = {lov.x, lov.y, lov.z, lov.w, hiv.x, hiv.y, hiv.z, hiv.w};

    int ws = i0 >> 5;
    int P = -1000000, N = 1000000;
    #pragma unroll
    for (int k = 0; k < 8; k++) {
        if (k < ws && cm[k]) P = (k << 5) + 31 - __clz(cm[k]);
        if (k > ws && cm[k] && N == 1000000) N = (k << 5) + __ffs(cm[k]) - 1;
    }
    unsigned int vw = cm[ws];

    #pragma unroll
    for (int r = 0; r < 4; r++) {
        int i = i0 + r, bi = i & 31;
        unsigned int below = vw & (0xFFFFFFFFu >> (31 - bi));
        unsigned int above = vw & (0xFFFFFFFFu << bi);
        int last = below ? ((ws << 5) + 31 - __clz(below)) : P;
        int nxt  = above ? ((ws << 5) + __ffs(above) - 1)  : N;
        int f = min(min(i - last, nxt - i), 10000);      // BIG clip (1e4)
        u.f[u4][r][W + j] = (unsigned short)f;
    }
    __syncthreads();

    // exact min-plus (int arithmetic; identical values to reference for every
    // case where a seeded column is in range — guaranteed here), early exit
    float sd = 0.f, sp = 0.f, mxv = 0.f;
    #pragma unroll
    for (int r = 0; r < 4; r++) {
        const unsigned short* fr = u.f[u4][r];
        int f0 = fr[W + j];
        int m = f0 * f0;
        int o = 1;
        while (o * o < m && o < W) {
            int c1 = fr[W + j - o];
            int c2 = fr[W + j + o];
            int oo = o * o;
            m = min(m, c1 * c1 + oo);
            m = min(m, c2 * c2 + oo);
            o++;
        }
        float d = (m < LUTN) ? s_lut[m] : sqrtf((float)m);
        float pred = fast_sigmoid(xl[r]);
        sd += d;
        sp += pred * d;
        mxv = fmaxf(mxv, d);
    }

    // ====== deterministic reduction: warp -> unit -> block ==================
    #pragma unroll
    for (int o = 16; o; o >>= 1) {
        sd  += __shfl_down_sync(0xffffffffu, sd,  o);
        sp  += __shfl_down_sync(0xffffffffu, sp,  o);
        mxv  = fmaxf(mxv, __shfl_down_sync(0xffffffffu, mxv, o));
    }
    if (lane == 0) { rs[u4][w] = sd; rp[u4][w] = sp; rm[u4][w] = mxv; }
    __syncthreads();
    if (ut == 0) {
        float S = 0.f, Pp = 0.f, M = 0.f;
        #pragma unroll
        for (int k = 0; k < 8; k++) {
            S += rs[u4][k]; Pp += rp[u4][k]; M = fmaxf(M, rm[u4][k]);
        }
        us[u4] = S; up[u4] = Pp; um[u4] = M;
    }
    __syncthreads();
    if (tid == 0) {
        float S = 0.f, Pp = 0.f, M = 0.f;
        #pragma unroll
        for (int k = 0; k < 4; k++) { S += us[k]; Pp += up[k]; M = fmaxf(M, um[k]); }
        g_d[bid] = S; g_pd[bid] = Pp; g_mx[bid] = M;
        __threadfence();
        amLast = (atomicAdd(&g_t, 1u) == GRID - 1);
    }
    __syncthreads();
    if (!amLast) return;

    // ====== Final reduction (last block): warp w = image w, lanes 0..15 =====
    if (w < 8 && u4 == 0) {               // warps 0..7 only
        double sdd = 0.0, spp = 0.0;
        float mxx = 0.f;
        if (lane < 16) {
            int idx = w * 16 + lane;      // 16 partials per image
            sdd = (double)g_d[idx];
            spp = (double)g_pd[idx];
            mxx = g_mx[idx];
        }
        #pragma unroll
        for (int o = 8; o; o >>= 1) {
            sdd += __shfl_down_sync(0xffffffffu, sdd, o);
            spp += __shfl_down_sync(0xffffffffu, spp, o);
            mxx  = fmaxf(mxx, __shfl_down_sync(0xffffffffu, mxx, o));
        }
        if (lane == 0)
            sper[w] = spp / (sdd + 1e-7 * ((double)mxx + 1e-7));
    }
    __syncthreads();
    if (tid == 0) {
        double acc = 0.0;
        #pragma unroll
        for (int k = 0; k < BB; k++) acc += sper[k];
        out[0] = (float)(acc / BB);
        g_t = 0;                          // reset for next graph replay
        g_barA = 0;
    }
}

extern "C" void kernel_launch(void* const* d_in, const int* in_sizes, int n_in,
                              void* d_out, int out_size) {
    const float* logits = (const float*)d_in[0];
    const int*   target = (const int*)d_in[1];
    float* out = (float*)d_out;

    k_fused<<<GRID, 1024>>>(logits, target, out);
}

// round 14
// speedup vs baseline: 1.4470x; 1.1186x over previous
#include <cuda_runtime.h>
#include <math.h>

#define BB 8
#define H 256
#define W 256
#define NPIX (H*W)
#define GRID 512
#define PREP_BLOCKS 64
#define FINAL_BID 64
#define LUTN 1024

// Scratch (device globals — no allocation allowed)
__device__ unsigned int g_cm[BB*W*8];   // column seed masks: [(b*W+j)*8 + slab]
__device__ float g_pd[GRID];            // per-block sum(pred*d)
__device__ float g_d [GRID];            // per-block sum(d)
__device__ float g_mx[GRID];            // per-block max(d)
__device__ unsigned int g_barA = 0;     // phase-A arrival counter
__device__ unsigned int g_t = 0;        // phase-B completion counter (RED target)

union SmemU {
    struct {                            // phase A
        unsigned int tb[H];
        unsigned int hm[H];
        unsigned int bd[H];
        unsigned int Lm[8], Rm[8];
    } a;
    struct {                            // phase B: 4 rows, each padded [W|W|W]
        float s[4][3*W];
    } b;
};

__device__ __forceinline__ float fast_sigmoid(float x) {
    float th;
    asm("tanh.approx.f32 %0, %1;" : "=f"(th) : "f"(x * 0.5f));
    return fmaf(0.5f, th, 0.5f);
}

__global__ void __launch_bounds__(256, 4)
k_fused(const float* __restrict__ logits, const int* __restrict__ target,
        float* __restrict__ out) {
    __shared__ SmemU u;
    __shared__ float s_lut[LUTN];
    __shared__ float rs[8], rp[8], rm[8];

    int bid = blockIdx.x;
    int tid = threadIdx.x;
    int w = tid >> 5, lane = tid & 31;

    int pb = bid >> 6;                  // phase-B image
    int i0 = (bid & 63) * 4;            // phase-B first row (same 32-row slab)
    int j = tid;                        // phase-B column
    float xl[4];
    bool isPrep = (bid < PREP_BLOCKS);

    // Non-prep blocks prefetch logits immediately (hides DRAM under the spin).
    if (!isPrep) {
        #pragma unroll
        for (int r = 0; r < 4; r++)
            xl[r] = logits[(pb * H + i0 + r) * W + j];
    }

    // ====== Phase A (blocks 0..63): (image, 32-col group) full stripe =======
    if (isPrep) {
        int b = bid >> 3;
        int g = bid & 7;
        const int* t = target + b * NPIX;
        int colbase = g << 5;

        // pack: warp w packs rows 32w..32w+31; batch 16 loads -> 16 ballots
        #pragma unroll
        for (int batch = 0; batch < 2; batch++) {
            int v[16];
            #pragma unroll
            for (int r = 0; r < 16; r++) {
                int i = (w << 5) + batch * 16 + r;
                v[r] = t[i * W + colbase + lane];
            }
            #pragma unroll
            for (int r = 0; r < 16; r++) {
                unsigned int m = __ballot_sync(0xffffffffu, v[r] != 0);
                if (lane == 0) u.a.tb[(w << 5) + batch * 16 + r] = m;
            }
        }
        // halo columns (lane = row within slab)
        {
            int i = (w << 5) + lane;
            int Lv = (g > 0) ? t[i * W + colbase - 1]  : 0;
            int Rv = (g < 7) ? t[i * W + colbase + 32] : 0;
            unsigned int lm  = __ballot_sync(0xffffffffu, Lv != 0);
            unsigned int rm2 = __ballot_sync(0xffffffffu, Rv != 0);
            if (lane == 0) { u.a.Lm[w] = lm; u.a.Rm[w] = rm2; }
        }
        __syncthreads();                                 // (1)

        // horizontal 3-AND (thread = row)
        {
            int i = tid;
            unsigned int c  = u.a.tb[i];
            unsigned int Lb = (u.a.Lm[i >> 5] >> (i & 31)) & 1u;
            unsigned int Rb = (u.a.Rm[i >> 5] >> (i & 31)) & 1u;
            unsigned int lf = (c << 1) | Lb;
            unsigned int rt = (c >> 1) | (Rb << 31);
            u.a.hm[i] = c & lf & rt;
        }
        __syncthreads();                                 // (2)

        // vertical 3-AND -> erosion; boundary = tb ^ er -> separate bd array
        {
            int i = tid;
            unsigned int er = (i > 0 && i < H - 1)
                            ? (u.a.hm[i - 1] & u.a.hm[i] & u.a.hm[i + 1]) : 0u;
            if (g == 0) er &= ~1u;
            if (g == 7) er &= ~(1u << 31);
            u.a.bd[i] = u.a.tb[i] ^ er;
        }
        __syncthreads();                                 // (3)

        // 32x32 bit transpose per warp; lane j gets column j's slab bits
        unsigned int word = u.a.bd[(w << 5) + lane];
        unsigned int v = 0u;
        #pragma unroll
        for (int jj = 0; jj < 32; jj++) {
            unsigned int bm = __ballot_sync(0xffffffffu, (word >> jj) & 1u);
            if (lane == jj) v = bm;
        }
        g_cm[((b * W) + colbase + lane) * 8 + w] = v;

        __threadfence();
        __syncthreads();
        if (tid == 0) atomicAdd(&g_barA, 1u);

        // prep blocks load their logits now (after phase A's critical path)
        #pragma unroll
        for (int r = 0; r < 4; r++)
            xl[r] = logits[(pb * H + i0 + r) * W + j];
    }

    // ====== Pre-barrier work with no phase-A dependency =====================
    #pragma unroll
    for (int k = 0; k < 4; k++) {       // sqrt LUT (exact sqrtf of integer m)
        int idx = tid + k * 256;
        s_lut[idx] = sqrtf((float)idx);
    }
    #pragma unroll
    for (int r = 0; r < 4; r++) {
        u.b.s[r][j] = 1e30f;            // left pad
        u.b.s[r][2 * W + j] = 1e30f;    // right pad
    }

    // ====== Grid barrier =====================================================
    if (tid == 0) {
        while (*(volatile unsigned int*)&g_barA < PREP_BLOCKS) __nanosleep(32);
    }
    __syncthreads();

    // ====== Phase B: vertical distance from bitmask + exact min-plus ========
    const uint4* cmp = (const uint4*)&g_cm[((pb * W) + j) * 8];
    uint4 lov = cmp[0], hiv = cmp[1];
    unsigned int cm[8] = {lov.x, lov.y, lov.z, lov.w, hiv.x, hiv.y, hiv.z, hiv.w};

    int ws = i0 >> 5;
    int P = -1000000, N = 1000000;
    #pragma unroll
    for (int k = 0; k < 8; k++) {
        if (k < ws && cm[k]) P = (k << 5) + 31 - __clz(cm[k]);
        if (k > ws && cm[k] && N == 1000000) N = (k << 5) + __ffs(cm[k]) - 1;
    }
    unsigned int vw = cm[ws];

    #pragma unroll
    for (int r = 0; r < 4; r++) {
        int i = i0 + r, bi = i & 31;
        unsigned int below = vw & (0xFFFFFFFFu >> (31 - bi));
        unsigned int above = vw & (0xFFFFFFFFu << bi);
        int last = below ? ((ws << 5) + 31 - __clz(below)) : P;
        int nxt  = above ? ((ws << 5) + __ffs(above) - 1)  : N;
        int f = min(min(i - last, nxt - i), 10000);      // BIG clip (1e4)
        u.b.s[r][W + j] = (float)(f * f);                // exact in fp32
    }
    __syncthreads();

    // exact min-plus per pixel, per-lane early exit; d via smem LUT
    float sd = 0.f, sp = 0.f, mxv = 0.f;
    #pragma unroll
    for (int r = 0; r < 4; r++) {
        const float* s = u.b.s[r];
        float m = s[W + j];
        int o = 1;
        while ((float)(o * o) < m) {
            float o2 = (float)(o * o);
            m = fminf(m, s[W + j - o] + o2);
            m = fminf(m, s[W + j + o] + o2);
            o++;
        }
        int mi = (int)m;
        float d = (mi < LUTN) ? s_lut[mi] : sqrtf(m);
        float pred = fast_sigmoid(xl[r]);
        sd += d;
        sp += pred * d;
        mxv = fmaxf(mxv, d);
    }

    // deterministic block reduction -> per-block partials
    #pragma unroll
    for (int o = 16; o; o >>= 1) {
        sd  += __shfl_down_sync(0xffffffffu, sd,  o);
        sp  += __shfl_down_sync(0xffffffffu, sp,  o);
        mxv  = fmaxf(mxv, __shfl_down_sync(0xffffffffu, mxv, o));
    }
    if (lane == 0) { rs[w] = sd; rp[w] = sp; rm[w] = mxv; }
    __syncthreads();
    if (tid == 0) {
        float S = 0.f, Pp = 0.f, M = 0.f;
        #pragma unroll
        for (int k = 0; k < 8; k++) { S += rs[k]; Pp += rp[k]; M = fmaxf(M, rm[k]); }
        g_d[bid] = S; g_pd[bid] = Pp; g_mx[bid] = M;
        __threadfence();
        atomicAdd(&g_t, 1u);            // return unused -> REDG (no round trip)
    }

    // ====== Designated final block polls, then reduces ======================
    if (bid != FINAL_BID) return;
    if (tid == 0) {
        while (*(volatile unsigned int*)&g_t < GRID) __nanosleep(64);
    }
    __syncthreads();
    __threadfence();                    // order poll observe before partial reads

    {
        double sdd = 0.0, spp = 0.0;
        float mxx = 0.f;
        #pragma unroll
        for (int k = 0; k < 2; k++) {
            int rr = w * 64 + k * 32 + lane;
            sdd += (double)g_d[rr];
            spp += (double)g_pd[rr];
            mxx = fmaxf(mxx, g_mx[rr]);
        }
        #pragma unroll
        for (int o = 16; o; o >>= 1) {
            sdd += __shfl_down_sync(0xffffffffu, sdd, o);
            spp += __shfl_down_sync(0xffffffffu, spp, o);
            mxx  = fmaxf(mxx, __shfl_down_sync(0xffffffffu, mxx, o));
        }
        __shared__ double sper[BB];
        if (lane == 0)
            sper[w] = spp / (sdd + 1e-7 * ((double)mxx + 1e-7));
        __syncthreads();
        if (tid == 0) {
            double acc = 0.0;
            #pragma unroll
            for (int k = 0; k < BB; k++) acc += sper[k];
            out[0] = (float)(acc / BB);
            g_t = 0;                    // reset for next graph replay
            g_barA = 0;
        }
    }
}

extern "C" void kernel_launch(void* const* d_in, const int* in_sizes, int n_in,
                              void* d_out, int out_size) {
    const float* logits = (const float*)d_in[0];
    const int*   target = (const int*)d_in[1];
    float* out = (float*)d_out;

    k_fused<<<GRID, 256>>>(logits, target, out);
}

// round 15
// speedup vs baseline: 1.4501x; 1.0021x over previous
#include <cuda_runtime.h>
#include <math.h>

#define BB 8
#define H 256
#define W 256
#define NPIX (H*W)
#define GRID 512
#define PREP_BLOCKS 64
#define FINAL_BID 64
#define LUTN 1024

// Scratch (device globals — no allocation allowed)
__device__ unsigned int g_cm[BB*W*8];   // column seed masks: [(b*W+j)*8 + slab]
__device__ float g_pd[GRID];            // per-block sum(pred*d)
__device__ float g_d [GRID];            // per-block sum(d)
__device__ float g_mx[GRID];            // per-block max(d)
__device__ unsigned int g_barA[BB] = {};// per-image phase-A arrival counters
__device__ unsigned int g_t = 0;        // phase-B completion counter (RED target)

union SmemU {
    struct {                            // phase A
        unsigned int tb[H];
        unsigned int hm[H];
        unsigned int bd[H];
        unsigned int Lm[8], Rm[8];
    } a;
    struct {                            // phase B: 4 rows, each padded [W|W|W]
        float s[4][3*W];
    } b;
};

__device__ __forceinline__ float fast_sigmoid(float x) {
    float th;
    asm("tanh.approx.f32 %0, %1;" : "=f"(th) : "f"(x * 0.5f));
    return fmaf(0.5f, th, 0.5f);
}

__global__ void __launch_bounds__(256, 4)
k_fused(const float* __restrict__ logits, const int* __restrict__ target,
        float* __restrict__ out) {
    __shared__ SmemU u;
    __shared__ float s_lut[LUTN];
    __shared__ float rs[8], rp[8], rm[8];

    int bid = blockIdx.x;
    int tid = threadIdx.x;
    int w = tid >> 5, lane = tid & 31;

    int pb = bid >> 6;                  // phase-B image
    int i0 = (bid & 63) * 4;            // phase-B first row (same 32-row slab)
    int j = tid;                        // phase-B column
    float xl[4];
    bool isPrep = (bid < PREP_BLOCKS);

    // Non-prep blocks prefetch logits immediately (hides DRAM under the spin).
    if (!isPrep) {
        #pragma unroll
        for (int r = 0; r < 4; r++)
            xl[r] = logits[(pb * H + i0 + r) * W + j];
    }

    // ====== Phase A (blocks 0..63): (image, 32-col group) full stripe =======
    if (isPrep) {
        int b = bid >> 3;
        int g = bid & 7;
        const int* t = target + b * NPIX;
        int colbase = g << 5;

        // halo loads issued FIRST so they overlap the pack batches
        int Lv, Rv;
        {
            int i = (w << 5) + lane;
            Lv = (g > 0) ? t[i * W + colbase - 1]  : 0;
            Rv = (g < 7) ? t[i * W + colbase + 32] : 0;
        }

        // pack: warp w packs rows 32w..32w+31; batch 16 loads -> 16 ballots
        #pragma unroll
        for (int batch = 0; batch < 2; batch++) {
            int v[16];
            #pragma unroll
            for (int r = 0; r < 16; r++) {
                int i = (w << 5) + batch * 16 + r;
                v[r] = t[i * W + colbase + lane];
            }
            #pragma unroll
            for (int r = 0; r < 16; r++) {
                unsigned int m = __ballot_sync(0xffffffffu, v[r] != 0);
                if (lane == 0) u.a.tb[(w << 5) + batch * 16 + r] = m;
            }
        }
        // halo ballots (loads long since landed)
        {
            unsigned int lm  = __ballot_sync(0xffffffffu, Lv != 0);
            unsigned int rm2 = __ballot_sync(0xffffffffu, Rv != 0);
            if (lane == 0) { u.a.Lm[w] = lm; u.a.Rm[w] = rm2; }
        }
        __syncthreads();                                 // (1)

        // horizontal 3-AND (thread = row)
        {
            int i = tid;
            unsigned int c  = u.a.tb[i];
            unsigned int Lb = (u.a.Lm[i >> 5] >> (i & 31)) & 1u;
            unsigned int Rb = (u.a.Rm[i >> 5] >> (i & 31)) & 1u;
            unsigned int lf = (c << 1) | Lb;
            unsigned int rt = (c >> 1) | (Rb << 31);
            u.a.hm[i] = c & lf & rt;
        }
        __syncthreads();                                 // (2)

        // vertical 3-AND -> erosion; boundary = tb ^ er -> separate bd array
        {
            int i = tid;
            unsigned int er = (i > 0 && i < H - 1)
                            ? (u.a.hm[i - 1] & u.a.hm[i] & u.a.hm[i + 1]) : 0u;
            if (g == 0) er &= ~1u;
            if (g == 7) er &= ~(1u << 31);
            u.a.bd[i] = u.a.tb[i] ^ er;
        }
        __syncthreads();                                 // (3)

        // 32x32 bit transpose per warp; lane j gets column j's slab bits
        unsigned int word = u.a.bd[(w << 5) + lane];
        unsigned int v = 0u;
        #pragma unroll
        for (int jj = 0; jj < 32; jj++) {
            unsigned int bm = __ballot_sync(0xffffffffu, (word >> jj) & 1u);
            if (lane == jj) v = bm;
        }
        g_cm[((b * W) + colbase + lane) * 8 + w] = v;

        __threadfence();
        __syncthreads();
        if (tid == 0) atomicAdd(&g_barA[b], 1u);         // RED arrive (per image)

        // prep blocks load their logits now (after phase A's critical path)
        #pragma unroll
        for (int r = 0; r < 4; r++)
            xl[r] = logits[(pb * H + i0 + r) * W + j];
    }

    // ====== Pre-barrier work with no phase-A dependency =====================
    #pragma unroll
    for (int k = 0; k < 4; k++) {       // sqrt LUT (exact sqrtf of integer m)
        int idx = tid + k * 256;
        s_lut[idx] = sqrtf((float)idx);
    }
    #pragma unroll
    for (int r = 0; r < 4; r++) {
        u.b.s[r][j] = 1e30f;            // left pad
        u.b.s[r][2 * W + j] = 1e30f;    // right pad
    }

    // ====== Per-image barrier: wait only for OUR image's 8 prep blocks ======
    if (tid == 0) {
        while (*(volatile unsigned int*)&g_barA[pb] < 8u) __nanosleep(32);
    }
    __syncthreads();

    // ====== Phase B: vertical distance from bitmask + exact min-plus ========
    const uint4* cmp = (const uint4*)&g_cm[((pb * W) + j) * 8];
    uint4 lov = cmp[0], hiv = cmp[1];
    unsigned int cm[8] = {lov.x, lov.y, lov.z, lov.w, hiv.x, hiv.y, hiv.z, hiv.w};

    int ws = i0 >> 5;
    int P = -1000000, N = 1000000;
    #pragma unroll
    for (int k = 0; k < 8; k++) {
        if (k < ws && cm[k]) P = (k << 5) + 31 - __clz(cm[k]);
        if (k > ws && cm[k] && N == 1000000) N = (k << 5) + __ffs(cm[k]) - 1;
    }
    unsigned int vw = cm[ws];

    #pragma unroll
    for (int r = 0; r < 4; r++) {
        int i = i0 + r, bi = i & 31;
        unsigned int below = vw & (0xFFFFFFFFu >> (31 - bi));
        unsigned int above = vw & (0xFFFFFFFFu << bi);
        int last = below ? ((ws << 5) + 31 - __clz(below)) : P;
        int nxt  = above ? ((ws << 5) + __ffs(above) - 1)  : N;
        int f = min(min(i - last, nxt - i), 10000);      // BIG clip (1e4)
        u.b.s[r][W + j] = (float)(f * f);                // exact in fp32
    }
    __syncthreads();

    // exact min-plus per pixel, per-lane early exit; d via smem LUT
    float sd = 0.f, sp = 0.f, mxv = 0.f;
    #pragma unroll
    for (int r = 0; r < 4; r++) {
        const float* s = u.b.s[r];
        float m = s[W + j];
        int o = 1;
        while ((float)(o * o) < m) {
            float o2 = (float)(o * o);
            m = fminf(m, s[W + j - o] + o2);
            m = fminf(m, s[W + j + o] + o2);
            o++;
        }
        int mi = (int)m;
        float d = (mi < LUTN) ? s_lut[mi] : sqrtf(m);
        float pred = fast_sigmoid(xl[r]);
        sd += d;
        sp += pred * d;
        mxv = fmaxf(mxv, d);
    }

    // deterministic block reduction -> per-block partials
    #pragma unroll
    for (int o = 16; o; o >>= 1) {
        sd  += __shfl_down_sync(0xffffffffu, sd,  o);
        sp  += __shfl_down_sync(0xffffffffu, sp,  o);
        mxv  = fmaxf(mxv, __shfl_down_sync(0xffffffffu, mxv, o));
    }
    if (lane == 0) { rs[w] = sd; rp[w] = sp; rm[w] = mxv; }
    __syncthreads();
    if (tid == 0) {
        float S = 0.f, Pp = 0.f, M = 0.f;
        #pragma unroll
        for (int k = 0; k < 8; k++) { S += rs[k]; Pp += rp[k]; M = fmaxf(M, rm[k]); }
        g_d[bid] = S; g_pd[bid] = Pp; g_mx[bid] = M;
        __threadfence();
        atomicAdd(&g_t, 1u);            // return unused -> REDG (no round trip)
    }

    // ====== Designated final block polls, then reduces ======================
    if (bid != FINAL_BID) return;
    if (tid == 0) {
        while (*(volatile unsigned int*)&g_t < GRID) __nanosleep(64);
    }
    __syncthreads();
    __threadfence();                    // order poll observe before partial reads

    {
        double sdd = 0.0, spp = 0.0;
        float mxx = 0.f;
        #pragma unroll
        for (int k = 0; k < 2; k++) {
            int rr = w * 64 + k * 32 + lane;
            sdd += (double)g_d[rr];
            spp += (double)g_pd[rr];
            mxx = fmaxf(mxx, g_mx[rr]);
        }
        #pragma unroll
        for (int o = 16; o; o >>= 1) {
            sdd += __shfl_down_sync(0xffffffffu, sdd, o);
            spp += __shfl_down_sync(0xffffffffu, spp, o);
            mxx  = fmaxf(mxx, __shfl_down_sync(0xffffffffu, mxx, o));
        }
        __shared__ double sper[BB];
        if (lane == 0)
            sper[w] = spp / (sdd + 1e-7 * ((double)mxx + 1e-7));
        __syncthreads();
        if (tid == 0) {
            double acc = 0.0;
            #pragma unroll
            for (int k = 0; k < BB; k++) acc += sper[k];
            out[0] = (float)(acc / BB);
            g_t = 0;                    // reset for next graph replay
            #pragma unroll
            for (int k = 0; k < BB; k++) g_barA[k] = 0;
        }
    }
}

extern "C" void kernel_launch(void* const* d_in, const int* in_sizes, int n_in,
                              void* d_out, int out_size) {
    const float* logits = (const float*)d_in[0];
    const int*   target = (const int*)d_in[1];
    float* out = (float*)d_out;

    k_fused<<<GRID, 256>>>(logits, target, out);
}

// round 16
// speedup vs baseline: 1.5178x; 1.0467x over previous
#include <cuda_runtime.h>
#include <math.h>

#define BB 8
#define H 256
#define W 256
#define NPIX (H*W)
#define GRID 256
#define PREP_BLOCKS 64
#define FINAL_BID 64
#define LUTN 1024

// Scratch (device globals — no allocation allowed)
__device__ unsigned int g_cm[BB*W*8];   // column seed masks: [(b*W+j)*8 + slab]
__device__ float g_pd[GRID];            // per-block sum(pred*d)
__device__ float g_d [GRID];            // per-block sum(d)
__device__ float g_mx[GRID];            // per-block max(d)
__device__ unsigned int g_barA = 0;     // phase-A arrival counter
__device__ unsigned int g_t = 0;        // phase-B completion counter (RED target)

union SmemU {
    struct {                            // phase A
        unsigned int tb[H];
        unsigned int hm[H];
        unsigned int bd[H];
        unsigned int Lm[8], Rm[8];
    } a;
    struct {                            // phase B: 8 rows, each padded [W|W|W]
        float s[8][3*W];
    } b;
};

__device__ __forceinline__ float fast_sigmoid(float x) {
    float th;
    asm("tanh.approx.f32 %0, %1;" : "=f"(th) : "f"(x * 0.5f));
    return fmaf(0.5f, th, 0.5f);
}

__global__ void __launch_bounds__(256, 4)
k_fused(const float* __restrict__ logits, const int* __restrict__ target,
        float* __restrict__ out) {
    __shared__ SmemU u;
    __shared__ float s_lut[LUTN];
    __shared__ float rs[8], rp[8], rm[8];

    int bid = blockIdx.x;
    int tid = threadIdx.x;
    int w = tid >> 5, lane = tid & 31;

    int pb = bid >> 5;                  // phase-B image (32 blocks per image)
    int i0 = (bid & 31) * 8;            // first of 8 rows (same 32-row slab)
    int j = tid;                        // phase-B column
    float xl[8];
    bool isPrep = (bid < PREP_BLOCKS);

    // Non-prep blocks prefetch logits immediately (hides DRAM under the spin).
    if (!isPrep) {
        #pragma unroll
        for (int r = 0; r < 8; r++)
            xl[r] = logits[(pb * H + i0 + r) * W + j];
    }

    // ====== Phase A (blocks 0..63): (image, 32-col group) full stripe =======
    if (isPrep) {
        int b = bid >> 3;
        int g = bid & 7;
        const int* t = target + b * NPIX;
        int colbase = g << 5;

        // halo loads issued FIRST so they overlap the pack batches
        int Lv, Rv;
        {
            int i = (w << 5) + lane;
            Lv = (g > 0) ? t[i * W + colbase - 1]  : 0;
            Rv = (g < 7) ? t[i * W + colbase + 32] : 0;
        }

        // pack: warp w packs rows 32w..32w+31; batch 16 loads -> 16 ballots
        #pragma unroll
        for (int batch = 0; batch < 2; batch++) {
            int v[16];
            #pragma unroll
            for (int r = 0; r < 16; r++) {
                int i = (w << 5) + batch * 16 + r;
                v[r] = t[i * W + colbase + lane];
            }
            #pragma unroll
            for (int r = 0; r < 16; r++) {
                unsigned int m = __ballot_sync(0xffffffffu, v[r] != 0);
                if (lane == 0) u.a.tb[(w << 5) + batch * 16 + r] = m;
            }
        }
        // halo ballots (loads long since landed)
        {
            unsigned int lm  = __ballot_sync(0xffffffffu, Lv != 0);
            unsigned int rm2 = __ballot_sync(0xffffffffu, Rv != 0);
            if (lane == 0) { u.a.Lm[w] = lm; u.a.Rm[w] = rm2; }
        }
        __syncthreads();                                 // (1)

        // horizontal 3-AND (thread = row)
        {
            int i = tid;
            unsigned int c  = u.a.tb[i];
            unsigned int Lb = (u.a.Lm[i >> 5] >> (i & 31)) & 1u;
            unsigned int Rb = (u.a.Rm[i >> 5] >> (i & 31)) & 1u;
            unsigned int lf = (c << 1) | Lb;
            unsigned int rt = (c >> 1) | (Rb << 31);
            u.a.hm[i] = c & lf & rt;
        }
        __syncthreads();                                 // (2)

        // vertical 3-AND -> erosion; boundary = tb ^ er -> separate bd array
        {
            int i = tid;
            unsigned int er = (i > 0 && i < H - 1)
                            ? (u.a.hm[i - 1] & u.a.hm[i] & u.a.hm[i + 1]) : 0u;
            if (g == 0) er &= ~1u;
            if (g == 7) er &= ~(1u << 31);
            u.a.bd[i] = u.a.tb[i] ^ er;
        }
        __syncthreads();                                 // (3)

        // 32x32 bit transpose per warp; lane j gets column j's slab bits
        unsigned int word = u.a.bd[(w << 5) + lane];
        unsigned int v = 0u;
        #pragma unroll
        for (int jj = 0; jj < 32; jj++) {
            unsigned int bm = __ballot_sync(0xffffffffu, (word >> jj) & 1u);
            if (lane == jj) v = bm;
        }
        g_cm[((b * W) + colbase + lane) * 8 + w] = v;

        __threadfence();
        __syncthreads();
        if (tid == 0) atomicAdd(&g_barA, 1u);

        // prep blocks load their logits now (after phase A's critical path)
        #pragma unroll
        for (int r = 0; r < 8; r++)
            xl[r] = logits[(pb * H + i0 + r) * W + j];
    }

    // ====== Pre-barrier work with no phase-A dependency =====================
    #pragma unroll
    for (int k = 0; k < 4; k++) {       // sqrt LUT (exact sqrtf of integer m)
        int idx = tid + k * 256;
        s_lut[idx] = sqrtf((float)idx);
    }
    #pragma unroll
    for (int r = 0; r < 8; r++) {
        u.b.s[r][j] = 1e30f;            // left pad
        u.b.s[r][2 * W + j] = 1e30f;    // right pad
    }

    // ====== Grid barrier =====================================================
    if (tid == 0) {
        while (*(volatile unsigned int*)&g_barA < PREP_BLOCKS) __nanosleep(32);
    }
    __syncthreads();

    // ====== Phase B: vertical distance from bitmask + exact min-plus ========
    const uint4* cmp = (const uint4*)&g_cm[((pb * W) + j) * 8];
    uint4 lov = cmp[0], hiv = cmp[1];
    unsigned int cm[8] = {lov.x, lov.y, lov.z, lov.w, hiv.x, hiv.y, hiv.z, hiv.w};

    int ws = i0 >> 5;
    int P = -1000000, N = 1000000;
    #pragma unroll
    for (int k = 0; k < 8; k++) {
        if (k < ws && cm[k]) P = (k << 5) + 31 - __clz(cm[k]);
        if (k > ws && cm[k] && N == 1000000) N = (k << 5) + __ffs(cm[k]) - 1;
    }
    unsigned int vw = cm[ws];

    #pragma unroll
    for (int r = 0; r < 8; r++) {
        int i = i0 + r, bi = i & 31;
        unsigned int below = vw & (0xFFFFFFFFu >> (31 - bi));
        unsigned int above = vw & (0xFFFFFFFFu << bi);
        int last = below ? ((ws << 5) + 31 - __clz(below)) : P;
        int nxt  = above ? ((ws << 5) + __ffs(above) - 1)  : N;
        int f = min(min(i - last, nxt - i), 10000);      // BIG clip (1e4)
        u.b.s[r][W + j] = (float)(f * f);                // exact in fp32
    }
    __syncthreads();

    // exact min-plus per pixel, per-lane early exit; d via smem LUT
    float sd = 0.f, sp = 0.f, mxv = 0.f;
    #pragma unroll
    for (int r = 0; r < 8; r++) {
        const float* s = u.b.s[r];
        float m = s[W + j];
        int o = 1;
        while ((float)(o * o) < m) {
            float o2 = (float)(o * o);
            m = fminf(m, s[W + j - o] + o2);
            m = fminf(m, s[W + j + o] + o2);
            o++;
        }
        int mi = (int)m;
        float d = (mi < LUTN) ? s_lut[mi] : sqrtf(m);
        float pred = fast_sigmoid(xl[r]);
        sd += d;
        sp += pred * d;
        mxv = fmaxf(mxv, d);
    }

    // deterministic block reduction -> per-block partials
    #pragma unroll
    for (int o = 16; o; o >>= 1) {
        sd  += __shfl_down_sync(0xffffffffu, sd,  o);
        sp  += __shfl_down_sync(0xffffffffu, sp,  o);
        mxv  = fmaxf(mxv, __shfl_down_sync(0xffffffffu, mxv, o));
    }
    if (lane == 0) { rs[w] = sd; rp[w] = sp; rm[w] = mxv; }
    __syncthreads();
    if (tid == 0) {
        float S = 0.f, Pp = 0.f, M = 0.f;
        #pragma unroll
        for (int k = 0; k < 8; k++) { S += rs[k]; Pp += rp[k]; M = fmaxf(M, rm[k]); }
        g_d[bid] = S; g_pd[bid] = Pp; g_mx[bid] = M;
        __threadfence();
        atomicAdd(&g_t, 1u);            // return unused -> REDG (no round trip)
    }

    // ====== Designated final block polls, then reduces ======================
    if (bid != FINAL_BID) return;
    if (tid == 0) {
        while (*(volatile unsigned int*)&g_t < GRID) __nanosleep(64);
    }
    __syncthreads();
    __threadfence();                    // order poll observe before partial reads

    {
        // warp w = image w; lane reads the image's 32 block-partials directly
        double sdd = 0.0, spp = 0.0;
        float mxx = 0.f;
        {
            int rr = w * 32 + lane;
            sdd = (double)g_d[rr];
            spp = (double)g_pd[rr];
            mxx = g_mx[rr];
        }
        #pragma unroll
        for (int o = 16; o; o >>= 1) {
            sdd += __shfl_down_sync(0xffffffffu, sdd, o);
            spp += __shfl_down_sync(0xffffffffu, spp, o);
            mxx  = fmaxf(mxx, __shfl_down_sync(0xffffffffu, mxx, o));
        }
        __shared__ double sper[BB];
        if (lane == 0)
            sper[w] = spp / (sdd + 1e-7 * ((double)mxx + 1e-7));
        __syncthreads();
        if (tid == 0) {
            double acc = 0.0;
            #pragma unroll
            for (int k = 0; k < BB; k++) acc += sper[k];
            out[0] = (float)(acc / BB);
            g_t = 0;                    // reset for next graph replay
            g_barA = 0;
        }
    }
}

extern "C" void kernel_launch(void* const* d_in, const int* in_sizes, int n_in,
                              void* d_out, int out_size) {
    const float* logits = (const float*)d_in[0];
    const int*   target = (const int*)d_in[1];
    float* out = (float*)d_out;

    k_fused<<<GRID, 256>>>(logits, target, out);
}